// round 4
// baseline (speedup 1.0000x reference)
#include <cuda_runtime.h>
#include <math.h>

#define NN 50000
#define NE 800000
#define ET (NE + NN)
#define DI 128
#define DH 64
#define DOUT 40
#define SLOPE 0.2f

#define SCB 1024
#define NBLK ((NN + SCB - 1) / SCB)   // 49

// ---------------- scratch (device globals) ----------------
__device__ float g_h[NN * DH];
__device__ float g_as[NN];
__device__ float g_ad[NN];
__device__ float g_h1o[NN * DH];
__device__ int   g_deg[NN];
__device__ int   g_rowptr[NN + 1];
__device__ int   g_pos[NN];
__device__ int   g_bsum[NBLK];
__device__ int   g_boff[NBLK];
__device__ int   g_esrc[ET];
__device__ float g_We1[DI * (DH + 2)];
__device__ float g_We2[DH * (DOUT + 2)];

__device__ __forceinline__ void edge_sd(int t, const int* __restrict__ ei, int& s, int& d) {
    if (t < NE) { s = ei[t]; d = ei[NE + t]; }
    else        { s = t - NE; d = s; }
}

// ---------------- weight prep: Wext = [W | W@asrc | W@adst] ----------------
__global__ void prep_kernel(const float* __restrict__ W1, const float* __restrict__ as1,
                            const float* __restrict__ ad1,
                            const float* __restrict__ W2, const float* __restrict__ as2,
                            const float* __restrict__ ad2) {
    int t = threadIdx.x;   // 256
    for (int i = t; i < DI * DH; i += 256) {
        int k = i / DH, j = i % DH;
        g_We1[k * (DH + 2) + j] = W1[i];
    }
    for (int k = t; k < DI; k += 256) {
        float sa = 0.f, sd = 0.f;
        for (int j = 0; j < DH; j++) {
            float w = W1[k * DH + j];
            sa += w * as1[j];
            sd += w * ad1[j];
        }
        g_We1[k * (DH + 2) + DH] = sa;
        g_We1[k * (DH + 2) + DH + 1] = sd;
    }
    for (int i = t; i < DH * DOUT; i += 256) {
        int k = i / DOUT, j = i % DOUT;
        g_We2[k * (DOUT + 2) + j] = W2[i];
    }
    for (int k = t; k < DH; k += 256) {
        float sa = 0.f, sd = 0.f;
        for (int j = 0; j < DOUT; j++) {
            float w = W2[k * DOUT + j];
            sa += w * as2[j];
            sd += w * ad2[j];
        }
        g_We2[k * (DOUT + 2) + DOUT] = sa;
        g_We2[k * (DOUT + 2) + DOUT + 1] = sd;
    }
}

// ---------------- CSR build ----------------
__global__ void hist_kernel(const int* __restrict__ ei) {
    int t = blockIdx.x * blockDim.x + threadIdx.x;
    if (t >= ET) return;
    int s, d; edge_sd(t, ei, s, d);
    atomicAdd(&g_deg[d], 1);
}

__global__ void scan_local_kernel() {
    __shared__ int sp[SCB];
    int t = threadIdx.x;
    int i = blockIdx.x * SCB + t;
    int v = (i < NN) ? g_deg[i] : 0;
    sp[t] = v;
    __syncthreads();
    for (int off = 1; off < SCB; off <<= 1) {
        int u = (t >= off) ? sp[t - off] : 0;
        __syncthreads();
        sp[t] += u;
        __syncthreads();
    }
    if (i < NN) g_rowptr[i] = sp[t] - v;
    if (t == SCB - 1) g_bsum[blockIdx.x] = sp[t];
}

__global__ void scan_bsum_kernel() {
    int lane = threadIdx.x & 31;
    int a = (lane < NBLK) ? g_bsum[lane] : 0;
    int b = (32 + lane < NBLK) ? g_bsum[32 + lane] : 0;
    int ia = a, ib = b;
#pragma unroll
    for (int off = 1; off < 32; off <<= 1) {
        int t0 = __shfl_up_sync(0xffffffffu, ia, off);
        int t1 = __shfl_up_sync(0xffffffffu, ib, off);
        if (lane >= off) { ia += t0; ib += t1; }
    }
    int tot0 = __shfl_sync(0xffffffffu, ia, 31);
    ib += tot0;
    if (lane < NBLK) g_boff[lane] = ia - a;
    if (32 + lane < NBLK) g_boff[32 + lane] = ib - b;
    int total = __shfl_sync(0xffffffffu, ib, 31);
    if (lane == 0) g_rowptr[NN] = total;
}

__global__ void add_off_kernel() {
    int i = blockIdx.x * blockDim.x + threadIdx.x;
    if (i >= NN) return;
    int r = g_rowptr[i] + g_boff[i >> 10];
    g_rowptr[i] = r;
    g_pos[i] = r;
}

__global__ void scatter_kernel(const int* __restrict__ ei) {
    int t = blockIdx.x * blockDim.x + threadIdx.x;
    if (t >= ET) return;
    int s, d; edge_sd(t, ei, s, d);
    int idx = atomicAdd(&g_pos[d], 1);
    g_esrc[idx] = s;
}

// ---------------- dense GEMM + attention dots ----------------
// H = X @ Wext where Wext has Dout feature cols + [wa | wd]. DoutE = Dout+2.
template <int Din, int DoutE, bool USE_X>
__global__ void gemm_kernel(const float* __restrict__ X) {
    __shared__ float sx[32 * Din];
    const float* src = USE_X ? X : g_h1o;
    const float* __restrict__ W = (DoutE == DH + 2) ? g_We1 : g_We2;
    const int Dout = DoutE - 2;
    int base = blockIdx.x * 32;
    int tid = threadIdx.x;
    const int nthr = DoutE * 4;

    for (int i = tid; i < 32 * (Din / 4); i += nthr) {
        int node = base + i / (Din / 4);
        float4 v = (node < NN) ? ((const float4*)src)[(size_t)node * (Din / 4) + (i % (Din / 4))]
                               : make_float4(0.f, 0.f, 0.f, 0.f);
        ((float4*)sx)[i] = v;
    }
    __syncthreads();

    int j = tid % DoutE;
    int n0 = tid / DoutE;
    float acc[8];
#pragma unroll
    for (int i = 0; i < 8; i++) acc[i] = 0.f;

    for (int k = 0; k < Din; k += 4) {
        float w0 = W[(k + 0) * DoutE + j];
        float w1 = W[(k + 1) * DoutE + j];
        float w2 = W[(k + 2) * DoutE + j];
        float w3 = W[(k + 3) * DoutE + j];
#pragma unroll
        for (int i = 0; i < 8; i++) {
            int node = n0 + i * 4;
            float4 xv = ((const float4*)sx)[node * (Din / 4) + (k >> 2)];
            acc[i] += xv.x * w0 + xv.y * w1 + xv.z * w2 + xv.w * w3;
        }
    }
#pragma unroll
    for (int i = 0; i < 8; i++) {
        int node = base + n0 + i * 4;
        if (node < NN) {
            if (j < Dout)           g_h[(size_t)node * Dout + j] = acc[i];
            else if (j == Dout)     g_as[node] = acc[i];
            else                    g_ad[node] = acc[i];
        }
    }
}

// ---------------- fused online-softmax aggregation (+epilogue) ----------------
// warp per dst node; single pass with running max + accumulator rescale.
template <int D, bool FINAL>
__global__ void agg_kernel(const float* __restrict__ b, float* __restrict__ out) {
    __shared__ float sp_p[8][32];
    __shared__ int   sp_s[8][32];
    int wl = threadIdx.x >> 5;
    int w = (blockIdx.x * blockDim.x + threadIdx.x) >> 5;
    int lane = threadIdx.x & 31;
    if (w >= NN) return;
    int beg = g_rowptr[w];
    int end = g_rowptr[w + 1];
    float ad_n = g_ad[w];

    const float2* __restrict__ h2 = (const float2*)g_h;
    float m = -INFINITY;
    float ssum = 0.f;
    float2 a = make_float2(0.f, 0.f);

    for (int j0 = beg; j0 < end; j0 += 32) {
        int j = j0 + lane;
        int s = 0;
        float e = -INFINITY;
        if (j < end) {
            s = g_esrc[j];
            e = g_as[s] + ad_n;
            e = e > 0.f ? e : SLOPE * e;
        }
        // tile max
        float tm = e;
#pragma unroll
        for (int off = 16; off; off >>= 1) tm = fmaxf(tm, __shfl_xor_sync(0xffffffffu, tm, off));
        float mnew = fmaxf(m, tm);
        float scale = __expf(m - mnew);     // 0 on first tile (m = -inf)
        ssum *= scale; a.x *= scale; a.y *= scale;
        m = mnew;

        float p = (j < end) ? __expf(e - m) : 0.f;
        ssum += p;
        sp_p[wl][lane] = p;
        sp_s[wl][lane] = s;
        __syncwarp();
        int cnt = min(32, end - j0);
        if (lane < D / 2) {
#pragma unroll 4
            for (int k = 0; k < cnt; k++) {
                float pk = sp_p[wl][k];
                int   sk = sp_s[wl][k];
                float2 hv = h2[(size_t)sk * (D / 2) + lane];
                a.x += pk * hv.x;
                a.y += pk * hv.y;
            }
        }
        __syncwarp();
    }
#pragma unroll
    for (int off = 16; off; off >>= 1) ssum += __shfl_xor_sync(0xffffffffu, ssum, off);
    float inv = 1.f / (ssum + 1e-16f);

    if (!FINAL) {
        float v0 = a.x * inv + b[2 * lane];
        float v1 = a.y * inv + b[2 * lane + 1];
        float2 o;
        o.x = v0 > 0.f ? v0 : 0.f;
        o.y = v1 > 0.f ? v1 : 0.f;
        ((float2*)g_h1o)[(size_t)w * (D / 2) + lane] = o;
    } else {
        float va = -INFINITY, vb = -INFINITY;
        if (lane < D / 2) {
            va = a.x * inv + b[2 * lane];
            vb = a.y * inv + b[2 * lane + 1];
        }
        float mx = fmaxf(va, vb);
#pragma unroll
        for (int off = 16; off; off >>= 1) mx = fmaxf(mx, __shfl_xor_sync(0xffffffffu, mx, off));
        float se = (lane < D / 2) ? (__expf(va - mx) + __expf(vb - mx)) : 0.f;
#pragma unroll
        for (int off = 16; off; off >>= 1) se += __shfl_xor_sync(0xffffffffu, se, off);
        float lse = mx + logf(se);
        if (lane < D / 2) {
            float2 o;
            o.x = va - lse;
            o.y = vb - lse;
            ((float2*)out)[(size_t)w * (D / 2) + lane] = o;
        }
    }
}

extern "C" void kernel_launch(void* const* d_in, const int* in_sizes, int n_in,
                              void* d_out, int out_size) {
    const float* x   = (const float*)d_in[0];
    const int*   ei  = (const int*)d_in[1];
    const float* W1  = (const float*)d_in[2];
    const float* as1 = (const float*)d_in[3];
    const float* ad1 = (const float*)d_in[4];
    const float* b1  = (const float*)d_in[5];
    const float* W2  = (const float*)d_in[6];
    const float* as2 = (const float*)d_in[7];
    const float* ad2 = (const float*)d_in[8];
    const float* b2  = (const float*)d_in[9];
    float* out = (float*)d_out;

    const int TB = 256;
    int grid_nodes32 = (NN + 31) / 32;
    int grid_warp_nodes = (NN * 32 + TB - 1) / TB;

    void* degPtr = nullptr;
    cudaGetSymbolAddress(&degPtr, g_deg);

    // ---------------- CSR build + weight prep ----------------
    cudaMemsetAsync(degPtr, 0, NN * sizeof(int));
    prep_kernel<<<1, 256>>>(W1, as1, ad1, W2, as2, ad2);
    hist_kernel<<<(ET + TB - 1) / TB, TB>>>(ei);
    scan_local_kernel<<<NBLK, SCB>>>();
    scan_bsum_kernel<<<1, 32>>>();
    add_off_kernel<<<(NN + TB - 1) / TB, TB>>>();
    scatter_kernel<<<(ET + TB - 1) / TB, TB>>>(ei);

    // ---------------- layer 1 ----------------
    gemm_kernel<DI, DH + 2, true><<<grid_nodes32, (DH + 2) * 4>>>(x);
    agg_kernel<DH, false><<<grid_warp_nodes, TB>>>(b1, nullptr);

    // ---------------- layer 2 ----------------
    gemm_kernel<DH, DOUT + 2, false><<<grid_nodes32, (DOUT + 2) * 4>>>(nullptr);
    agg_kernel<DOUT, true><<<grid_warp_nodes, TB>>>(b2, out);
}